// round 9
// baseline (speedup 1.0000x reference)
#include <cuda_runtime.h>
#include <cuda_fp16.h>

// ---------------------------------------------------------------------------
// GraphSAGE: out = mean_agg(x) @ W + x @ RW + bias    (N=100k, E=1.28M, D=64)
//   init  : cnt = 0, build WT fp16
//   combo : [blocks 0..CONVB)   x -> fp16 (g_xh)
//           [blocks CONVB..end) slot scatter: p=atomicAdd(cnt[r]); slot[r*96+p]=c
//   fused : 64-node tile: fp16 gather-mean (8-deep MLP) -> smem A[64][128],
//           tensor-core GEMM  C[64][64] = A @ WT^T  (mma.m16n8k16)
// No count/alloc kernels: fixed-capacity 96-slot buckets (P(deg>=96) ~ 1e-60
// for Poisson(12.8) degrees; stores clamped for safety).
// ---------------------------------------------------------------------------

#define NMAX 100000
#define EMAX 1280000
#define D 64
#define TN 64
#define SLOTS 96
#define CONVB 592    // convert blocks (4 per SM)

typedef unsigned long long ull;

__device__ int      g_cnt[NMAX];
__device__ int      g_slot[(size_t)NMAX * SLOTS];   // 38.4 MB
__device__ __half   g_xh[(size_t)NMAX * D];         // 12.8 MB fp16 copy of x
__device__ unsigned g_wt[64 * 64];                  // WT half2: [col j][k-pair kk]

// ---------------- init: zero cnt + build WT ----------------
__global__ void init_kernel(const float* __restrict__ Wm,
                            const float* __restrict__ RWm, int N) {
    int gid = blockIdx.x * blockDim.x + threadIdx.x;
    int stride = gridDim.x * blockDim.x;
    for (int k = gid; k < N; k += stride) g_cnt[k] = 0;

    // WT[j][kk] = half2( Wc[2kk][j], Wc[2kk+1][j] ),  Wc = concat(W; RW) rows
    if (gid < 64 * 64) {
        int j = gid >> 6, kk = gid & 63;
        int k0 = 2 * kk;
        float w0 = (k0 < 64) ? Wm[k0 * 64 + j] : RWm[(k0 - 64) * 64 + j];
        float w1 = (k0 + 1 < 64) ? Wm[(k0 + 1) * 64 + j] : RWm[(k0 + 1 - 64) * 64 + j];
        __half2 h = __floats2half2_rn(w0, w1);
        g_wt[gid] = *reinterpret_cast<unsigned*>(&h);
    }
}

// ---------------- combo: convert x->fp16 || slot scatter ----------------
__global__ void combo_kernel(const float4* __restrict__ x4, int n4,
                             const int* __restrict__ ei, int E) {
    int tid = threadIdx.x;
    if (blockIdx.x < CONVB) {
        // ---- convert partition ----
        int gid = blockIdx.x * 256 + tid;
        int stride = CONVB * 256;
        ull* dst = reinterpret_cast<ull*>(g_xh);
        for (int k = gid; k < n4; k += stride) {
            float4 v = x4[k];
            __half2 lo = __floats2half2_rn(v.x, v.y);
            __half2 hi = __floats2half2_rn(v.z, v.w);
            unsigned ulo = *reinterpret_cast<unsigned*>(&lo);
            unsigned uhi = *reinterpret_cast<unsigned*>(&hi);
            dst[k] = ((ull)uhi << 32) | (ull)ulo;
        }
    } else {
        // ---- scatter partition: 4 edges/thread ----
        int t = (blockIdx.x - CONVB) * 256 + tid;
        int e4 = t * 4;
        if (e4 + 4 <= E) {
            int4 r = *reinterpret_cast<const int4*>(ei + e4);
            int4 c = *reinterpret_cast<const int4*>(ei + E + e4);
            int p0 = atomicAdd(&g_cnt[r.x], 1);
            int p1 = atomicAdd(&g_cnt[r.y], 1);
            int p2 = atomicAdd(&g_cnt[r.z], 1);
            int p3 = atomicAdd(&g_cnt[r.w], 1);
            if (p0 < SLOTS) g_slot[r.x * SLOTS + p0] = c.x;
            if (p1 < SLOTS) g_slot[r.y * SLOTS + p1] = c.y;
            if (p2 < SLOTS) g_slot[r.z * SLOTS + p2] = c.z;
            if (p3 < SLOTS) g_slot[r.w * SLOTS + p3] = c.w;
        } else {
            for (int e = e4; e < E; e++) {
                int r = ei[e], c = ei[E + e];
                int p = atomicAdd(&g_cnt[r], 1);
                if (p < SLOTS) g_slot[r * SLOTS + p] = c;
            }
        }
    }
}

// ---------------- fused gather-mean + tensor-core GEMM ----------------
// smem (words = half2):
//   Ah[64 rows][68 words]  (row = node, halves k 0..127; 4-word row pad)
//   Wt[64 cols][68 words]  (col-major W^T, same pad)
#define ROWW 68

__global__ void __launch_bounds__(256) fused_kernel(
    const float* __restrict__ bias,
    float* __restrict__ out, int N)
{
    __shared__ unsigned Ah[64 * ROWW];
    __shared__ unsigned Wt[64 * ROWW];

    int tid = threadIdx.x, lane = tid & 31, w = tid >> 5;

    // stage WT (16 KB, repack with pad)
    for (int i = tid; i < 64 * 64; i += 256) {
        int j = i >> 6, kk = i & 63;
        Wt[j * ROWW + kk] = g_wt[i];
    }

    int nodeBase = blockIdx.x * TN;
    const unsigned* xw = reinterpret_cast<const unsigned*>(g_xh);  // 32 words/row

    // ---- phase 1: gather. warp w -> nodes w*8 .. w*8+7; MLP=8 ----
    for (int s = 0; s < 8; s++) {
        int nloc = w * 8 + s;
        int g = nodeBase + nloc;
        int d = 0, off = 0;
        if (g < N) {
            d = g_cnt[g];
            if (d > SLOTS) d = SLOTS;
            off = g * SLOTS;
        }
        float ax = 0.f, ay = 0.f;

        for (int base = 0; base < d; base += 32) {
            int m = d - base; if (m > 32) m = 32;
            int colv = (lane < m) ? g_slot[off + base + lane] : 0;
            int j = 0;
            for (; j + 8 <= m; j += 8) {
                int c0 = __shfl_sync(0xffffffffu, colv, j);
                int c1 = __shfl_sync(0xffffffffu, colv, j + 1);
                int c2 = __shfl_sync(0xffffffffu, colv, j + 2);
                int c3 = __shfl_sync(0xffffffffu, colv, j + 3);
                int c4 = __shfl_sync(0xffffffffu, colv, j + 4);
                int c5 = __shfl_sync(0xffffffffu, colv, j + 5);
                int c6 = __shfl_sync(0xffffffffu, colv, j + 6);
                int c7 = __shfl_sync(0xffffffffu, colv, j + 7);
                unsigned u0 = __ldg(&xw[c0 * 32 + lane]);
                unsigned u1 = __ldg(&xw[c1 * 32 + lane]);
                unsigned u2 = __ldg(&xw[c2 * 32 + lane]);
                unsigned u3 = __ldg(&xw[c3 * 32 + lane]);
                unsigned u4 = __ldg(&xw[c4 * 32 + lane]);
                unsigned u5 = __ldg(&xw[c5 * 32 + lane]);
                unsigned u6 = __ldg(&xw[c6 * 32 + lane]);
                unsigned u7 = __ldg(&xw[c7 * 32 + lane]);
                float2 f0 = __half22float2(*reinterpret_cast<__half2*>(&u0));
                float2 f1 = __half22float2(*reinterpret_cast<__half2*>(&u1));
                float2 f2 = __half22float2(*reinterpret_cast<__half2*>(&u2));
                float2 f3 = __half22float2(*reinterpret_cast<__half2*>(&u3));
                float2 f4 = __half22float2(*reinterpret_cast<__half2*>(&u4));
                float2 f5 = __half22float2(*reinterpret_cast<__half2*>(&u5));
                float2 f6 = __half22float2(*reinterpret_cast<__half2*>(&u6));
                float2 f7 = __half22float2(*reinterpret_cast<__half2*>(&u7));
                ax += ((f0.x + f1.x) + (f2.x + f3.x)) + ((f4.x + f5.x) + (f6.x + f7.x));
                ay += ((f0.y + f1.y) + (f2.y + f3.y)) + ((f4.y + f5.y) + (f6.y + f7.y));
            }
            for (; j < m; j++) {
                int c = __shfl_sync(0xffffffffu, colv, j);
                unsigned u = __ldg(&xw[c * 32 + lane]);
                float2 f = __half22float2(*reinterpret_cast<__half2*>(&u));
                ax += f.x; ay += f.y;
            }
        }
        float inv = 1.0f / (float)(d > 0 ? d : 1);
        __half2 h = __floats2half2_rn(ax * inv, ay * inv);
        Ah[nloc * ROWW + lane] = *reinterpret_cast<unsigned*>(&h);
        // self term (k 64..127) straight from fp16 x
        unsigned sv = (g < N) ? __ldg(&xw[(long)g * 32 + lane]) : 0u;
        Ah[nloc * ROWW + 32 + lane] = sv;
    }
    __syncthreads();

    // ---- phase 2: tensor-core GEMM ----
    int gq = lane >> 2, t4 = lane & 3;
    int mtile = w & 3, nhalf = w >> 2;
    int rowA0 = (mtile * 16 + gq) * ROWW;
    int rowA1 = rowA0 + 8 * ROWW;

    float acc[4][4];
    #pragma unroll
    for (int nt = 0; nt < 4; nt++) {
        int colbase = nhalf * 32 + nt * 8;
        float blo = __ldg(&bias[colbase + 2 * t4]);
        float bhi = __ldg(&bias[colbase + 2 * t4 + 1]);
        acc[nt][0] = blo; acc[nt][1] = bhi;
        acc[nt][2] = blo; acc[nt][3] = bhi;
    }

    #pragma unroll
    for (int k0w = 0; k0w < 64; k0w += 8) {   // 16 halves per step
        unsigned a0 = Ah[rowA0 + k0w + t4];
        unsigned a1 = Ah[rowA1 + k0w + t4];
        unsigned a2 = Ah[rowA0 + k0w + 4 + t4];
        unsigned a3 = Ah[rowA1 + k0w + 4 + t4];
        #pragma unroll
        for (int nt = 0; nt < 4; nt++) {
            int colw = (nhalf * 32 + nt * 8 + gq) * ROWW + k0w;
            unsigned b0 = Wt[colw + t4];
            unsigned b1 = Wt[colw + 4 + t4];
            asm volatile(
                "mma.sync.aligned.m16n8k16.row.col.f32.f16.f16.f32 "
                "{%0,%1,%2,%3}, {%4,%5,%6,%7}, {%8,%9}, {%0,%1,%2,%3};\n"
                : "+f"(acc[nt][0]), "+f"(acc[nt][1]),
                  "+f"(acc[nt][2]), "+f"(acc[nt][3])
                : "r"(a0), "r"(a1), "r"(a2), "r"(a3), "r"(b0), "r"(b1));
        }
    }

    // ---- store ----
    int n0 = nodeBase + mtile * 16 + gq;
    int n1 = n0 + 8;
    #pragma unroll
    for (int nt = 0; nt < 4; nt++) {
        int col = nhalf * 32 + nt * 8 + 2 * t4;
        if (n0 < N)
            *reinterpret_cast<float2*>(&out[(long)n0 * D + col]) =
                make_float2(acc[nt][0], acc[nt][1]);
        if (n1 < N)
            *reinterpret_cast<float2*>(&out[(long)n1 * D + col]) =
                make_float2(acc[nt][2], acc[nt][3]);
    }
}

// ---------------- launch ----------------
extern "C" void kernel_launch(void* const* d_in, const int* in_sizes, int n_in,
                              void* d_out, int out_size) {
    const float* x    = (const float*)d_in[0];
    const int*   ei   = (const int*)d_in[1];
    const float* W    = (const float*)d_in[2];
    const float* RW   = (const float*)d_in[3];
    const float* bias = (const float*)d_in[4];
    float* out = (float*)d_out;

    int N = in_sizes[0] / D;
    int E = in_sizes[1] / 2;
    if (N > NMAX) N = NMAX;
    if (E > EMAX) E = EMAX;

    init_kernel<<<400, 256>>>(W, RW, N);

    int scatter_blocks = (E / 4 + 255) / 256;   // 1250 for E=1.28M
    combo_kernel<<<CONVB + scatter_blocks, 256>>>(
        reinterpret_cast<const float4*>(x), N * (D / 4), ei, E);

    fused_kernel<<<(N + TN - 1) / TN, 256>>>(bias, out, N);
}

// round 13
// speedup vs baseline: 1.2986x; 1.2986x over previous
#include <cuda_runtime.h>
#include <cuda_fp16.h>

// ---------------------------------------------------------------------------
// GraphSAGE: out = mean_agg(x) @ W + x @ RW + bias    (N=100k, E=1.28M, D=64)
//   prep  : zero deg/total, x->fp16 (g_xh), build WT fp16 (g_wt)
//   count : deg[row]++           (4 edges/thread, int4 loads)
//   alloc : exclusive offsets via block scan + global atomic base;
//           writes g_offs and g_cur=offs (fill cursor)
//   fill  : p = atomicAdd(&g_cur[r]); csr[p] = c   (4 edges/thread, int4)
//   fused : 64-node tile: fp16 gather-mean with warp-wide metadata load and
//           double-buffered neighbor-list prefetch -> smem A[64][128],
//           tensor-core GEMM  C[64][64] = A @ WT^T  (mma.m16n8k16)
// ---------------------------------------------------------------------------

#define NMAX 100000
#define EMAX 1280000
#define D 64
#define TN 64

typedef unsigned long long ull;

__device__ int      g_deg[NMAX];
__device__ int      g_offs[NMAX];
__device__ int      g_cur[NMAX];
__device__ int      g_csr[EMAX];
__device__ int      g_total;
__device__ __half   g_xh[(size_t)NMAX * D];     // fp16 copy of x (12.8 MB)
__device__ unsigned g_wt[64 * 64];              // WT half2: [col j][k-pair kk]

// ---------------- prep: zeros + conversions ----------------
__global__ void prep_kernel(const float4* __restrict__ x4, int n4,
                            const float* __restrict__ Wm,
                            const float* __restrict__ RWm, int N) {
    int gid = blockIdx.x * blockDim.x + threadIdx.x;
    int stride = gridDim.x * blockDim.x;

    if (gid == 0) g_total = 0;
    for (int k = gid; k < N; k += stride) g_deg[k] = 0;

    // x -> fp16 (packed 4 floats -> 4 halves per iter)
    ull* dst = reinterpret_cast<ull*>(g_xh);
    for (int k = gid; k < n4; k += stride) {
        float4 v = x4[k];
        __half2 lo = __floats2half2_rn(v.x, v.y);
        __half2 hi = __floats2half2_rn(v.z, v.w);
        unsigned ulo = *reinterpret_cast<unsigned*>(&lo);
        unsigned uhi = *reinterpret_cast<unsigned*>(&hi);
        dst[k] = ((ull)uhi << 32) | (ull)ulo;
    }

    // WT[j][kk] = half2( Wc[2kk][j], Wc[2kk+1][j] ),  Wc = concat(W; RW) rows
    if (gid < 64 * 64) {
        int j = gid >> 6, kk = gid & 63;
        int k0 = 2 * kk;
        float w0 = (k0 < 64) ? Wm[k0 * 64 + j] : RWm[(k0 - 64) * 64 + j];
        float w1 = (k0 + 1 < 64) ? Wm[(k0 + 1) * 64 + j] : RWm[(k0 + 1 - 64) * 64 + j];
        __half2 h = __floats2half2_rn(w0, w1);
        g_wt[gid] = *reinterpret_cast<unsigned*>(&h);
    }
}

// ---------------- count: 4 edges/thread ----------------
__global__ void count_kernel(const int* __restrict__ ei, int E) {
    int t = blockIdx.x * blockDim.x + threadIdx.x;
    int e4 = t * 4;
    if (e4 + 4 <= E) {
        int4 r = *reinterpret_cast<const int4*>(ei + e4);
        atomicAdd(&g_deg[r.x], 1);
        atomicAdd(&g_deg[r.y], 1);
        atomicAdd(&g_deg[r.z], 1);
        atomicAdd(&g_deg[r.w], 1);
    } else {
        for (int e = e4; e < E; e++) atomicAdd(&g_deg[ei[e]], 1);
    }
}

// ---------------- alloc: block-scan + global atomic base ----------------
__global__ void alloc_kernel(int N) {
    int t = threadIdx.x;
    int i = blockIdx.x * 256 + t;
    int d = (i < N) ? g_deg[i] : 0;
    int lane = t & 31, wrp = t >> 5;

    int v = d;
    #pragma unroll
    for (int s = 1; s < 32; s <<= 1) {
        int u = __shfl_up_sync(0xffffffffu, v, s);
        if (lane >= s) v += u;
    }
    __shared__ int wsum[8];
    __shared__ int gbase;
    if (lane == 31) wsum[wrp] = v;
    __syncthreads();
    if (t == 0) {
        int acc = 0;
        #pragma unroll
        for (int k = 0; k < 8; k++) { int tmp = wsum[k]; wsum[k] = acc; acc += tmp; }
        gbase = atomicAdd(&g_total, acc);
    }
    __syncthreads();
    if (i < N) {
        int off = gbase + wsum[wrp] + v - d;
        g_offs[i] = off;
        g_cur[i]  = off;   // fill cursor pre-seeded with the offset
    }
}

// ---------------- fill: 4 edges/thread, cursor carries offset ----------------
__global__ void fill_kernel(const int* __restrict__ ei, int E) {
    int t = blockIdx.x * blockDim.x + threadIdx.x;
    int e4 = t * 4;
    if (e4 + 4 <= E) {
        int4 r = *reinterpret_cast<const int4*>(ei + e4);
        int4 c = *reinterpret_cast<const int4*>(ei + E + e4);
        int p0 = atomicAdd(&g_cur[r.x], 1);
        int p1 = atomicAdd(&g_cur[r.y], 1);
        int p2 = atomicAdd(&g_cur[r.z], 1);
        int p3 = atomicAdd(&g_cur[r.w], 1);
        g_csr[p0] = c.x;
        g_csr[p1] = c.y;
        g_csr[p2] = c.z;
        g_csr[p3] = c.w;
    } else {
        for (int e = e4; e < E; e++) {
            int r = ei[e], c = ei[E + e];
            int p = atomicAdd(&g_cur[r], 1);
            g_csr[p] = c;
        }
    }
}

// ---------------- fused gather-mean + tensor-core GEMM ----------------
// smem (words = half2):
//   Ah[64 rows][68 words]  (row = node, halves k 0..127; 4-word row pad)
//   Wt[64 cols][68 words]  (col-major W^T, same pad)
#define ROWW 68

__global__ void __launch_bounds__(256) fused_kernel(
    const float* __restrict__ bias,
    float* __restrict__ out, int N)
{
    __shared__ unsigned Ah[64 * ROWW];
    __shared__ unsigned Wt[64 * ROWW];

    int tid = threadIdx.x, lane = tid & 31, w = tid >> 5;

    // stage WT (16 KB, repack with pad)
    for (int i = tid; i < 64 * 64; i += 256) {
        int j = i >> 6, kk = i & 63;
        Wt[j * ROWW + kk] = g_wt[i];
    }

    int nodeBase = blockIdx.x * TN;
    const unsigned* xw = reinterpret_cast<const unsigned*>(g_xh);  // 32 words/row

    // ---- phase 1: gather. warp w -> nodes w*8 .. w*8+7 ----
    // Warp-wide metadata: lanes 0-7 carry deg, lanes 8-15 carry offs.
    int gbase = nodeBase + w * 8;
    int meta = 0;
    {
        int gi = gbase + (lane & 7);
        if (gi < N) {
            if (lane < 8)       meta = g_deg[gi];
            else if (lane < 16) meta = g_offs[gi];
        }
    }
    // prefetch first node's neighbor list
    int colv_cur;
    {
        int d0 = __shfl_sync(0xffffffffu, meta, 0);
        int o0 = __shfl_sync(0xffffffffu, meta, 8);
        int m0 = d0 < 32 ? d0 : 32;
        colv_cur = (gbase < N && lane < m0) ? g_csr[o0 + lane] : 0;
    }

    #pragma unroll
    for (int s = 0; s < 8; s++) {
        int g = gbase + s;
        int d = __shfl_sync(0xffffffffu, meta, s);
        if (g >= N) d = 0;
        int off = __shfl_sync(0xffffffffu, meta, 8 + s);

        // prefetch next node's list while we crunch this one
        int colv_nxt = 0;
        if (s < 7) {
            int dn = __shfl_sync(0xffffffffu, meta, s + 1);
            int on = __shfl_sync(0xffffffffu, meta, 9 + s);
            int mn = dn < 32 ? dn : 32;
            colv_nxt = ((gbase + s + 1) < N && lane < mn) ? g_csr[on + lane] : 0;
        }

        float ax = 0.f, ay = 0.f;
        int m = d < 32 ? d : 32;
        {
            int j = 0;
            for (; j + 8 <= m; j += 8) {
                int c0 = __shfl_sync(0xffffffffu, colv_cur, j);
                int c1 = __shfl_sync(0xffffffffu, colv_cur, j + 1);
                int c2 = __shfl_sync(0xffffffffu, colv_cur, j + 2);
                int c3 = __shfl_sync(0xffffffffu, colv_cur, j + 3);
                int c4 = __shfl_sync(0xffffffffu, colv_cur, j + 4);
                int c5 = __shfl_sync(0xffffffffu, colv_cur, j + 5);
                int c6 = __shfl_sync(0xffffffffu, colv_cur, j + 6);
                int c7 = __shfl_sync(0xffffffffu, colv_cur, j + 7);
                unsigned u0 = __ldg(&xw[c0 * 32 + lane]);
                unsigned u1 = __ldg(&xw[c1 * 32 + lane]);
                unsigned u2 = __ldg(&xw[c2 * 32 + lane]);
                unsigned u3 = __ldg(&xw[c3 * 32 + lane]);
                unsigned u4 = __ldg(&xw[c4 * 32 + lane]);
                unsigned u5 = __ldg(&xw[c5 * 32 + lane]);
                unsigned u6 = __ldg(&xw[c6 * 32 + lane]);
                unsigned u7 = __ldg(&xw[c7 * 32 + lane]);
                float2 f0 = __half22float2(*reinterpret_cast<__half2*>(&u0));
                float2 f1 = __half22float2(*reinterpret_cast<__half2*>(&u1));
                float2 f2 = __half22float2(*reinterpret_cast<__half2*>(&u2));
                float2 f3 = __half22float2(*reinterpret_cast<__half2*>(&u3));
                float2 f4 = __half22float2(*reinterpret_cast<__half2*>(&u4));
                float2 f5 = __half22float2(*reinterpret_cast<__half2*>(&u5));
                float2 f6 = __half22float2(*reinterpret_cast<__half2*>(&u6));
                float2 f7 = __half22float2(*reinterpret_cast<__half2*>(&u7));
                ax += ((f0.x + f1.x) + (f2.x + f3.x)) + ((f4.x + f5.x) + (f6.x + f7.x));
                ay += ((f0.y + f1.y) + (f2.y + f3.y)) + ((f4.y + f5.y) + (f6.y + f7.y));
            }
            for (; j < m; j++) {
                int c = __shfl_sync(0xffffffffu, colv_cur, j);
                unsigned u = __ldg(&xw[c * 32 + lane]);
                float2 f = __half22float2(*reinterpret_cast<__half2*>(&u));
                ax += f.x; ay += f.y;
            }
        }
        // rare extra chunks (d > 32)
        for (int base = 32; base < d; base += 32) {
            int mm = d - base; if (mm > 32) mm = 32;
            int colv = (lane < mm) ? g_csr[off + base + lane] : 0;
            for (int j = 0; j < mm; j++) {
                int c = __shfl_sync(0xffffffffu, colv, j);
                unsigned u = __ldg(&xw[c * 32 + lane]);
                float2 f = __half22float2(*reinterpret_cast<__half2*>(&u));
                ax += f.x; ay += f.y;
            }
        }

        float inv = 1.0f / (float)(d > 0 ? d : 1);
        __half2 h = __floats2half2_rn(ax * inv, ay * inv);
        int nloc = w * 8 + s;
        Ah[nloc * ROWW + lane] = *reinterpret_cast<unsigned*>(&h);
        // self term (k 64..127) straight from fp16 x
        unsigned sv = (g < N) ? __ldg(&xw[(long)g * 32 + lane]) : 0u;
        Ah[nloc * ROWW + 32 + lane] = sv;

        colv_cur = colv_nxt;
    }
    __syncthreads();

    // ---- phase 2: tensor-core GEMM ----
    int gq = lane >> 2, t4 = lane & 3;
    int mtile = w & 3, nhalf = w >> 2;
    int rowA0 = (mtile * 16 + gq) * ROWW;
    int rowA1 = rowA0 + 8 * ROWW;

    float acc[4][4];
    #pragma unroll
    for (int nt = 0; nt < 4; nt++) {
        int colbase = nhalf * 32 + nt * 8;
        float blo = __ldg(&bias[colbase + 2 * t4]);
        float bhi = __ldg(&bias[colbase + 2 * t4 + 1]);
        acc[nt][0] = blo; acc[nt][1] = bhi;
        acc[nt][2] = blo; acc[nt][3] = bhi;
    }

    #pragma unroll
    for (int k0w = 0; k0w < 64; k0w += 8) {   // 16 halves per step
        unsigned a0 = Ah[rowA0 + k0w + t4];
        unsigned a1 = Ah[rowA1 + k0w + t4];
        unsigned a2 = Ah[rowA0 + k0w + 4 + t4];
        unsigned a3 = Ah[rowA1 + k0w + 4 + t4];
        #pragma unroll
        for (int nt = 0; nt < 4; nt++) {
            int colw = (nhalf * 32 + nt * 8 + gq) * ROWW + k0w;
            unsigned b0 = Wt[colw + t4];
            unsigned b1 = Wt[colw + 4 + t4];
            asm volatile(
                "mma.sync.aligned.m16n8k16.row.col.f32.f16.f16.f32 "
                "{%0,%1,%2,%3}, {%4,%5,%6,%7}, {%8,%9}, {%0,%1,%2,%3};\n"
                : "+f"(acc[nt][0]), "+f"(acc[nt][1]),
                  "+f"(acc[nt][2]), "+f"(acc[nt][3])
                : "r"(a0), "r"(a1), "r"(a2), "r"(a3), "r"(b0), "r"(b1));
        }
    }

    // ---- store ----
    int n0 = nodeBase + mtile * 16 + gq;
    int n1 = n0 + 8;
    #pragma unroll
    for (int nt = 0; nt < 4; nt++) {
        int col = nhalf * 32 + nt * 8 + 2 * t4;
        if (n0 < N)
            *reinterpret_cast<float2*>(&out[(long)n0 * D + col]) =
                make_float2(acc[nt][0], acc[nt][1]);
        if (n1 < N)
            *reinterpret_cast<float2*>(&out[(long)n1 * D + col]) =
                make_float2(acc[nt][2], acc[nt][3]);
    }
}

// ---------------- launch ----------------
extern "C" void kernel_launch(void* const* d_in, const int* in_sizes, int n_in,
                              void* d_out, int out_size) {
    const float* x    = (const float*)d_in[0];
    const int*   ei   = (const int*)d_in[1];
    const float* W    = (const float*)d_in[2];
    const float* RW   = (const float*)d_in[3];
    const float* bias = (const float*)d_in[4];
    float* out = (float*)d_out;

    int N = in_sizes[0] / D;
    int E = in_sizes[1] / 2;
    if (N > NMAX) N = NMAX;
    if (E > EMAX) E = EMAX;

    prep_kernel<<<1024, 256>>>(reinterpret_cast<const float4*>(x),
                               N * (D / 4), W, RW, N);
    count_kernel<<<(E / 4 + 255) / 256, 256>>>(ei, E);
    alloc_kernel<<<(N + 255) / 256, 256>>>(N);
    fill_kernel<<<(E / 4 + 255) / 256, 256>>>(ei, E);
    fused_kernel<<<(N + TN - 1) / TN, 256>>>(bias, out, N);
}